// round 10
// baseline (speedup 1.0000x reference)
#include <cuda_runtime.h>
#include <cstdint>

// Problem constants
#define NN       131072
#define MDIM     64
#define KDIM     8
#define WTILE_N  8                   // n's per warp-tile
#define NTILES   (NN / WTILE_N)      // 16384
#define MCHUNK   4                   // m's staged per chunk (row chunk = 128B = 1 line)
#define NCHUNK   (MDIM / MCHUNK)     // 16
#define NSTRIDE  36                  // 32 data floats + 4 pad (36 % 32 == 4 -> conflict-free)
#define THREADS  128
#define GRIDB    912                 // 152 SMs * 6 resident blocks
#define NWARPS   (GRIDB * 4)         // 3648 persistent warps
#define WARR     (WTILE_N * NSTRIDE) // 288 floats per array per stage
#define WBUF     (4 * WARR)          // 1152 floats per stage (4 arrays)
#define WSM      (2 * WBUF)          // 2304 floats per warp (double buffered)

__device__ float g_partials[NWARPS];
__device__ unsigned int g_count = 0;      // self-resetting ticket counter

// ---- f32x2 packed-FMA helpers (FFMA2 is only reachable via PTX) ----
__device__ __forceinline__ unsigned long long pack2(float lo, float hi) {
    unsigned long long r;
    asm("mov.b64 %0, {%1, %2};" : "=l"(r) : "f"(lo), "f"(hi));
    return r;
}
__device__ __forceinline__ unsigned long long ffma2(unsigned long long a,
                                                    unsigned long long b,
                                                    unsigned long long c) {
    unsigned long long d;
    asm("fma.rn.f32x2 %0, %1, %2, %3;" : "=l"(d) : "l"(a), "l"(b), "l"(c));
    return d;
}
__device__ __forceinline__ void unpack2(unsigned long long v, float& lo, float& hi) {
    asm("mov.b64 {%0, %1}, %2;" : "=f"(lo), "=f"(hi) : "l"(v));
}

// ---- cp.async helpers ----
__device__ __forceinline__ void cp_async16(uint32_t saddr, const float* gptr) {
    asm volatile("cp.async.cg.shared.global [%0], [%1], 16;" :: "r"(saddr), "l"(gptr));
}
__device__ __forceinline__ void cp_commit() {
    asm volatile("cp.async.commit_group;");
}
template<int N> __device__ __forceinline__ void cp_wait() {
    asm volatile("cp.async.wait_group %0;" :: "n"(N));
}

__global__ __launch_bounds__(THREADS)
void sumrate_main_kernel(const float* __restrict__ Hr, const float* __restrict__ Hi,
                         const float* __restrict__ Vr, const float* __restrict__ Vi,
                         const float* __restrict__ noise_p, float* __restrict__ out) {
    __shared__ __align__(16) float smem[4 * WSM];   // [warp][stage][array][8n*36]
    __shared__ float fred[4];
    __shared__ int slast;

    const int t    = threadIdx.x;
    const int lane = t & 31;
    const int wid  = t >> 5;
    const int wg   = blockIdx.x * 4 + wid;          // global persistent warp id

    const int n_l  = lane >> 2;     // 0..7  (compute: n within warp tile)
    const int k1h  = lane & 3;      // handles k1 = k1h and k1h+4

    // staging map: per chunk per array, 8 rows * 8 float4 = 64 float4 over 32 lanes
    const int nl0  = lane >> 3,  pos0 = lane & 7;   // rows 0..3
    const int nl1  = nl0 + 4,    pos1 = pos0;       // rows 4..7
    const int soff0 = nl0 * NSTRIDE + pos0 * 4;
    const int soff1 = nl1 * NSTRIDE + pos1 * 4;

    float* wsm = smem + wid * WSM;
    uint32_t wsm_u32;
    asm("{ .reg .u64 a; cvta.to.shared.u64 a, %1; cvt.u32.u64 %0, a; }"
        : "=r"(wsm_u32) : "l"(wsm));

    auto stage = [&](int tile, int c, int buf) {
        const int gb = tile * (WTILE_N * MDIM * KDIM) + c * (MCHUNK * KDIM);
        const int g0 = gb + nl0 * (MDIM * KDIM) + pos0 * 4;
        const int g1 = gb + nl1 * (MDIM * KDIM) + pos1 * 4;
        const uint32_t sb = wsm_u32 + (uint32_t)(buf * WBUF) * 4u;
        cp_async16(sb + (uint32_t)(0 * WARR + soff0) * 4u, Hr + g0);
        cp_async16(sb + (uint32_t)(0 * WARR + soff1) * 4u, Hr + g1);
        cp_async16(sb + (uint32_t)(1 * WARR + soff0) * 4u, Hi + g0);
        cp_async16(sb + (uint32_t)(1 * WARR + soff1) * 4u, Hi + g1);
        cp_async16(sb + (uint32_t)(2 * WARR + soff0) * 4u, Vr + g0);
        cp_async16(sb + (uint32_t)(2 * WARR + soff1) * 4u, Vr + g1);
        cp_async16(sb + (uint32_t)(3 * WARR + soff0) * 4u, Vi + g0);
        cp_async16(sb + (uint32_t)(3 * WARR + soff1) * 4u, Vi + g1);
        cp_commit();
    };

    const float noise = __ldg(noise_p);
    float wsum = 0.0f;              // running rate sum over this warp's tiles

    // staged-ahead pointer (tile st, chunk sc); prologue: stage first chunk
    int st = wg, sc = 0;
    stage(st, 0, 0);
    sc = 1;
    unsigned gch = 0;               // global chunk counter (buffer parity)

    for (int tile = wg; tile < NTILES; tile += NWARPS) {
        // accumulators: [j][p] -> k1 = k1h + 4j, k2 pair (2p, 2p+1)
        unsigned long long re2[2][4] = {{0,0,0,0},{0,0,0,0}};
        unsigned long long im2[2][4] = {{0,0,0,0},{0,0,0,0}};

        #pragma unroll 1
        for (int c = 0; c < NCHUNK; ++c, ++gch) {
            // prefetch next chunk (possibly of the next tile) into the other buffer
            if (st < NTILES) {
                stage(st, sc, (int)((gch + 1u) & 1u));
                if (++sc == NCHUNK) { sc = 0; st += NWARPS; }
                cp_wait<1>();       // current chunk's group complete, next in flight
            } else {
                cp_wait<0>();
            }
            __syncwarp();           // all lanes' copies for chunk c visible to warp

            const float* sHr = wsm + (gch & 1u) * WBUF;
            const float* sHi = sHr + WARR;
            const float* sVr = sHr + 2 * WARR;
            const float* sVi = sHr + 3 * WARR;
            const int base0 = n_l * NSTRIDE;

            #pragma unroll
            for (int m = 0; m < MCHUNK; ++m) {
                const int b = base0 + m * KDIM;
                // H scalars: stride-4 across k1h -> conflict-free
                float hr0 = sHr[b + k1h];
                float hr1 = sHr[b + k1h + 4];
                float hi0 = sHi[b + k1h];
                float hi1 = sHi[b + k1h + 4];
                // V row (broadcast LDS.128 across the 4 threads of this n)
                ulonglong2 vra = *(const ulonglong2*)&sVr[b];
                ulonglong2 vrb = *(const ulonglong2*)&sVr[b + 4];
                ulonglong2 via = *(const ulonglong2*)&sVi[b];
                ulonglong2 vib = *(const ulonglong2*)&sVi[b + 4];

                {   // k1 = k1h
                    unsigned long long hr2  = pack2(hr0,  hr0);
                    unsigned long long hi2  = pack2(hi0,  hi0);
                    unsigned long long nhi2 = pack2(-hi0, -hi0);
                    re2[0][0] = ffma2(hr2, vra.x, re2[0][0]); re2[0][0] = ffma2(nhi2, via.x, re2[0][0]);
                    im2[0][0] = ffma2(hr2, via.x, im2[0][0]); im2[0][0] = ffma2(hi2,  vra.x, im2[0][0]);
                    re2[0][1] = ffma2(hr2, vra.y, re2[0][1]); re2[0][1] = ffma2(nhi2, via.y, re2[0][1]);
                    im2[0][1] = ffma2(hr2, via.y, im2[0][1]); im2[0][1] = ffma2(hi2,  vra.y, im2[0][1]);
                    re2[0][2] = ffma2(hr2, vrb.x, re2[0][2]); re2[0][2] = ffma2(nhi2, vib.x, re2[0][2]);
                    im2[0][2] = ffma2(hr2, vib.x, im2[0][2]); im2[0][2] = ffma2(hi2,  vrb.x, im2[0][2]);
                    re2[0][3] = ffma2(hr2, vrb.y, re2[0][3]); re2[0][3] = ffma2(nhi2, vib.y, re2[0][3]);
                    im2[0][3] = ffma2(hr2, vib.y, im2[0][3]); im2[0][3] = ffma2(hi2,  vrb.y, im2[0][3]);
                }
                {   // k1 = k1h + 4
                    unsigned long long hr2  = pack2(hr1,  hr1);
                    unsigned long long hi2  = pack2(hi1,  hi1);
                    unsigned long long nhi2 = pack2(-hi1, -hi1);
                    re2[1][0] = ffma2(hr2, vra.x, re2[1][0]); re2[1][0] = ffma2(nhi2, via.x, re2[1][0]);
                    im2[1][0] = ffma2(hr2, via.x, im2[1][0]); im2[1][0] = ffma2(hi2,  vra.x, im2[1][0]);
                    re2[1][1] = ffma2(hr2, vra.y, re2[1][1]); re2[1][1] = ffma2(nhi2, via.y, re2[1][1]);
                    im2[1][1] = ffma2(hr2, via.y, im2[1][1]); im2[1][1] = ffma2(hi2,  vra.y, im2[1][1]);
                    re2[1][2] = ffma2(hr2, vrb.x, re2[1][2]); re2[1][2] = ffma2(nhi2, vib.x, re2[1][2]);
                    im2[1][2] = ffma2(hr2, vib.x, im2[1][2]); im2[1][2] = ffma2(hi2,  vrb.x, im2[1][2]);
                    re2[1][3] = ffma2(hr2, vrb.y, re2[1][3]); re2[1][3] = ffma2(nhi2, vib.y, re2[1][3]);
                    im2[1][3] = ffma2(hr2, vib.y, im2[1][3]); im2[1][3] = ffma2(hi2,  vrb.y, im2[1][3]);
                }
            }
            __syncwarp();   // all lanes done reading this buffer before it is re-staged
        }

        // ---- epilogue: SINR + rate for this tile (per-lane: two k1 values) ----
        float rate = 0.0f;
        #pragma unroll
        for (int j = 0; j < 2; ++j) {
            float ref[8], imf[8];
            #pragma unroll
            for (int p = 0; p < 4; ++p) {
                unpack2(re2[j][p], ref[2 * p], ref[2 * p + 1]);
                unpack2(im2[j][p], imf[2 * p], imf[2 * p + 1]);
            }
            const int myk1 = k1h + 4 * j;
            float ssum = 0.0f, nom = 0.0f;
            #pragma unroll
            for (int k2 = 0; k2 < 8; ++k2) {
                float nr = ref[k2] * ref[k2] + imf[k2] * imf[k2];
                ssum += nr;
                if (k2 == myk1) nom = nr;   // SEL, no dynamic indexing
            }
            const float denom = ssum - nom + noise;
            rate += log2f(1.0f + nom / denom);
        }
        // warp-level deterministic reduction; lane 0 accumulates across tiles
        #pragma unroll
        for (int off = 16; off > 0; off >>= 1)
            rate += __shfl_down_sync(0xffffffffu, rate, off);
        wsum += rate;   // only lane 0's value is used
    }

    if (lane == 0) g_partials[wg] = wsum;
    __syncthreads();
    __threadfence();
    if (t == 0) {
        unsigned int ticket = atomicAdd(&g_count, 1u);
        slast = (ticket == (unsigned int)(GRIDB - 1));
    }
    __syncthreads();

    // ---- last block performs the fixed-order final reduction ----
    if (slast) {
        __threadfence();  // ensure all partials visible
        float s = 0.0f;
        for (int i = t; i < NWARPS; i += THREADS) s += g_partials[i];
        #pragma unroll
        for (int off = 16; off > 0; off >>= 1)
            s += __shfl_down_sync(0xffffffffu, s, off);
        if (lane == 0) fred[wid] = s;
        __syncthreads();
        if (t == 0) {
            float total = fred[0] + fred[1] + fred[2] + fred[3];
            out[0] = -total / (float)NN;   // loss = -mean over n of sum_k rate
            g_count = 0;                   // reset for next graph replay
        }
    }
}

extern "C" void kernel_launch(void* const* d_in, const int* in_sizes, int n_in,
                              void* d_out, int out_size) {
    const float* Hr  = (const float*)d_in[0];
    const float* Hi  = (const float*)d_in[1];
    const float* Vr  = (const float*)d_in[2];
    const float* Vi  = (const float*)d_in[3];
    const float* np_ = (const float*)d_in[4];
    float* out = (float*)d_out;

    sumrate_main_kernel<<<GRIDB, THREADS>>>(Hr, Hi, Vr, Vi, np_, out);
}

// round 11
// speedup vs baseline: 1.0863x; 1.0863x over previous
#include <cuda_runtime.h>
#include <cstdint>

// Problem constants
#define NN      131072
#define MDIM    64
#define KDIM    8
#define TILE_N  32                  // n's per tile
#define NTILES  (NN / TILE_N)       // 4096
#define MCHUNK  4                   // m's staged per chunk
#define NCHUNK  (MDIM / MCHUNK)     // 16
#define NSTRIDE 36                  // 32 data floats + 4 pad (36 % 32 == 4 -> conflict-free)
#define THREADS 128                 // 4 threads per n
#define GRIDB   912                 // 152 SMs * 6 resident blocks (persistent)
#define ARR_FLOATS (TILE_N * NSTRIDE)     // 1152
#define BUF_FLOATS (4 * ARR_FLOATS)       // 4608 floats per pipeline stage
#define SMEM_FLOATS (2 * BUF_FLOATS)      // 9216 floats (36864 B, static)

__device__ float g_partials[NTILES];      // per-tile partial: value independent of scheduling
__device__ unsigned int g_ticket = 0;     // dynamic tile dispatcher (self-resetting)
__device__ unsigned int g_done   = 0;     // block arrival counter (self-resetting)

// ---- f32x2 packed-FMA helpers (FFMA2 is only reachable via PTX) ----
__device__ __forceinline__ unsigned long long pack2(float lo, float hi) {
    unsigned long long r;
    asm("mov.b64 %0, {%1, %2};" : "=l"(r) : "f"(lo), "f"(hi));
    return r;
}
__device__ __forceinline__ unsigned long long ffma2(unsigned long long a,
                                                    unsigned long long b,
                                                    unsigned long long c) {
    unsigned long long d;
    asm("fma.rn.f32x2 %0, %1, %2, %3;" : "=l"(d) : "l"(a), "l"(b), "l"(c));
    return d;
}
__device__ __forceinline__ void unpack2(unsigned long long v, float& lo, float& hi) {
    asm("mov.b64 {%0, %1}, %2;" : "=f"(lo), "=f"(hi) : "l"(v));
}

// ---- cp.async helpers ----
__device__ __forceinline__ void cp_async16(uint32_t saddr, const float* gptr) {
    asm volatile("cp.async.cg.shared.global [%0], [%1], 16;" :: "r"(saddr), "l"(gptr));
}
__device__ __forceinline__ void cp_commit() {
    asm volatile("cp.async.commit_group;");
}
template<int N> __device__ __forceinline__ void cp_wait() {
    asm volatile("cp.async.wait_group %0;" :: "n"(N));
}

__global__ __launch_bounds__(THREADS)
void sumrate_main_kernel(const float* __restrict__ Hr, const float* __restrict__ Hi,
                         const float* __restrict__ Vr, const float* __restrict__ Vi,
                         const float* __restrict__ noise_p, float* __restrict__ out) {
    __shared__ __align__(16) float smem[SMEM_FLOATS];  // [2][4][ARR_FLOATS]
    __shared__ float wred[4];
    __shared__ int s_tile;
    __shared__ int slast;

    const int t       = threadIdx.x;
    const int n_local = t >> 2;     // 0..31
    const int k1h     = t & 3;      // handles k1 = k1h and k1h+4
    const int lane    = t & 31;
    const int wid     = t >> 5;

    // staging map: per chunk per array, 32 n * 8 float4 = 256 float4 over 128 threads (2 each)
    int soff0, soff1, nl0, nl1, pos0, pos1;
    {
        const int idx0 = t, idx1 = t + THREADS;
        nl0 = idx0 >> 3; pos0 = idx0 & 7;
        nl1 = idx1 >> 3; pos1 = idx1 & 7;
        soff0 = nl0 * NSTRIDE + pos0 * 4;
        soff1 = nl1 * NSTRIDE + pos1 * 4;
    }
    uint32_t smem_u32;
    asm("{ .reg .u64 a; cvta.to.shared.u64 a, %1; cvt.u32.u64 %0, a; }"
        : "=r"(smem_u32) : "l"(smem));

    auto stage = [&](int tile, int c, int buf) {
        const int n0 = tile * TILE_N;
        const int g0 = (n0 + nl0) * (MDIM * KDIM) + c * (MCHUNK * KDIM) + pos0 * 4;
        const int g1 = (n0 + nl1) * (MDIM * KDIM) + c * (MCHUNK * KDIM) + pos1 * 4;
        const uint32_t sb = smem_u32 + (uint32_t)(buf * BUF_FLOATS) * 4u;
        cp_async16(sb + (uint32_t)(0 * ARR_FLOATS + soff0) * 4u, Hr + g0);
        cp_async16(sb + (uint32_t)(0 * ARR_FLOATS + soff1) * 4u, Hr + g1);
        cp_async16(sb + (uint32_t)(1 * ARR_FLOATS + soff0) * 4u, Hi + g0);
        cp_async16(sb + (uint32_t)(1 * ARR_FLOATS + soff1) * 4u, Hi + g1);
        cp_async16(sb + (uint32_t)(2 * ARR_FLOATS + soff0) * 4u, Vr + g0);
        cp_async16(sb + (uint32_t)(2 * ARR_FLOATS + soff1) * 4u, Vr + g1);
        cp_async16(sb + (uint32_t)(3 * ARR_FLOATS + soff0) * 4u, Vi + g0);
        cp_async16(sb + (uint32_t)(3 * ARR_FLOATS + soff1) * 4u, Vi + g1);
        cp_commit();
    };

    const float noise = __ldg(noise_p);

    // ---- persistent loop: dynamic tile dispatch (deterministic via per-tile partials) ----
    while (true) {
        if (t == 0) s_tile = (int)atomicAdd(&g_ticket, 1u);
        __syncthreads();
        const int tile = s_tile;
        if (tile >= NTILES) break;

        // accumulators: [j][p] -> k1 = k1h + 4j, k2 pair (2p, 2p+1)
        unsigned long long re2[2][4] = {{0,0,0,0},{0,0,0,0}};
        unsigned long long im2[2][4] = {{0,0,0,0},{0,0,0,0}};

        stage(tile, 0, 0);   // prologue: chunk 0 into buffer 0

        #pragma unroll 1
        for (int c = 0; c < NCHUNK; ++c) {
            cp_wait<0>();        // this thread's copies of chunk c arrived
            __syncthreads();     // publishes chunk c AND certifies buffer (c+1)&1 free
            if (c + 1 < NCHUNK) stage(tile, c + 1, (c + 1) & 1);

            const float* sHr = smem + (c & 1) * BUF_FLOATS;
            const float* sHi = sHr + ARR_FLOATS;
            const float* sVr = sHr + 2 * ARR_FLOATS;
            const float* sVi = sHr + 3 * ARR_FLOATS;
            const int base0 = n_local * NSTRIDE;

            #pragma unroll
            for (int m = 0; m < MCHUNK; ++m) {
                const int b = base0 + m * KDIM;
                // H scalars: stride-4 across k1h -> conflict-free
                float hr0 = sHr[b + k1h];
                float hr1 = sHr[b + k1h + 4];
                float hi0 = sHi[b + k1h];
                float hi1 = sHi[b + k1h + 4];
                // V row (broadcast LDS.128 across the 4 threads of this n)
                ulonglong2 vra = *(const ulonglong2*)&sVr[b];
                ulonglong2 vrb = *(const ulonglong2*)&sVr[b + 4];
                ulonglong2 via = *(const ulonglong2*)&sVi[b];
                ulonglong2 vib = *(const ulonglong2*)&sVi[b + 4];

                {   // k1 = k1h
                    unsigned long long hr2  = pack2(hr0,  hr0);
                    unsigned long long hi2  = pack2(hi0,  hi0);
                    unsigned long long nhi2 = pack2(-hi0, -hi0);
                    re2[0][0] = ffma2(hr2, vra.x, re2[0][0]); re2[0][0] = ffma2(nhi2, via.x, re2[0][0]);
                    im2[0][0] = ffma2(hr2, via.x, im2[0][0]); im2[0][0] = ffma2(hi2,  vra.x, im2[0][0]);
                    re2[0][1] = ffma2(hr2, vra.y, re2[0][1]); re2[0][1] = ffma2(nhi2, via.y, re2[0][1]);
                    im2[0][1] = ffma2(hr2, via.y, im2[0][1]); im2[0][1] = ffma2(hi2,  vra.y, im2[0][1]);
                    re2[0][2] = ffma2(hr2, vrb.x, re2[0][2]); re2[0][2] = ffma2(nhi2, vib.x, re2[0][2]);
                    im2[0][2] = ffma2(hr2, vib.x, im2[0][2]); im2[0][2] = ffma2(hi2,  vrb.x, im2[0][2]);
                    re2[0][3] = ffma2(hr2, vrb.y, re2[0][3]); re2[0][3] = ffma2(nhi2, vib.y, re2[0][3]);
                    im2[0][3] = ffma2(hr2, vib.y, im2[0][3]); im2[0][3] = ffma2(hi2,  vrb.y, im2[0][3]);
                }
                {   // k1 = k1h + 4
                    unsigned long long hr2  = pack2(hr1,  hr1);
                    unsigned long long hi2  = pack2(hi1,  hi1);
                    unsigned long long nhi2 = pack2(-hi1, -hi1);
                    re2[1][0] = ffma2(hr2, vra.x, re2[1][0]); re2[1][0] = ffma2(nhi2, via.x, re2[1][0]);
                    im2[1][0] = ffma2(hr2, via.x, im2[1][0]); im2[1][0] = ffma2(hi2,  vra.x, im2[1][0]);
                    re2[1][1] = ffma2(hr2, vra.y, re2[1][1]); re2[1][1] = ffma2(nhi2, via.y, re2[1][1]);
                    im2[1][1] = ffma2(hr2, via.y, im2[1][1]); im2[1][1] = ffma2(hi2,  vra.y, im2[1][1]);
                    re2[1][2] = ffma2(hr2, vrb.x, re2[1][2]); re2[1][2] = ffma2(nhi2, vib.x, re2[1][2]);
                    im2[1][2] = ffma2(hr2, vib.x, im2[1][2]); im2[1][2] = ffma2(hi2,  vrb.x, im2[1][2]);
                    re2[1][3] = ffma2(hr2, vrb.y, re2[1][3]); re2[1][3] = ffma2(nhi2, vib.y, re2[1][3]);
                    im2[1][3] = ffma2(hr2, vib.y, im2[1][3]); im2[1][3] = ffma2(hi2,  vrb.y, im2[1][3]);
                }
            }
        }

        // ---- epilogue: SINR + rate for this tile (per-thread: two k1 values) ----
        float rate = 0.0f;
        #pragma unroll
        for (int j = 0; j < 2; ++j) {
            float ref[8], imf[8];
            #pragma unroll
            for (int p = 0; p < 4; ++p) {
                unpack2(re2[j][p], ref[2 * p], ref[2 * p + 1]);
                unpack2(im2[j][p], imf[2 * p], imf[2 * p + 1]);
            }
            const int myk1 = k1h + 4 * j;
            float ssum = 0.0f, nom = 0.0f;
            #pragma unroll
            for (int k2 = 0; k2 < 8; ++k2) {
                float nr = ref[k2] * ref[k2] + imf[k2] * imf[k2];
                ssum += nr;
                if (k2 == myk1) nom = nr;   // SEL, no dynamic indexing
            }
            const float denom = ssum - nom + noise;
            rate += log2f(1.0f + nom / denom);
        }

        // deterministic per-tile reduction (order fixed regardless of which block runs it)
        #pragma unroll
        for (int off = 16; off > 0; off >>= 1)
            rate += __shfl_down_sync(0xffffffffu, rate, off);
        if (lane == 0) wred[wid] = rate;
        __syncthreads();
        if (t == 0) g_partials[tile] = wred[0] + wred[1] + wred[2] + wred[3];
    }

    // ---- last arriving block does the fixed-order final reduction ----
    if (t == 0) {
        __threadfence();                      // publish this block's partials
        unsigned int k = atomicAdd(&g_done, 1u);
        slast = (k == (unsigned int)(GRIDB - 1));
    }
    __syncthreads();

    if (slast) {
        __threadfence();  // all partials visible
        float s = 0.0f;
        for (int i = t; i < NTILES; i += THREADS) s += g_partials[i];
        #pragma unroll
        for (int off = 16; off > 0; off >>= 1)
            s += __shfl_down_sync(0xffffffffu, s, off);
        if (lane == 0) wred[wid] = s;
        __syncthreads();
        if (t == 0) {
            float total = wred[0] + wred[1] + wred[2] + wred[3];
            out[0] = -total / (float)NN;   // loss = -mean over n of sum_k rate
            g_ticket = 0;                  // reset for next graph replay
            g_done   = 0;
        }
    }
}

extern "C" void kernel_launch(void* const* d_in, const int* in_sizes, int n_in,
                              void* d_out, int out_size) {
    const float* Hr  = (const float*)d_in[0];
    const float* Hi  = (const float*)d_in[1];
    const float* Vr  = (const float*)d_in[2];
    const float* Vi  = (const float*)d_in[3];
    const float* np_ = (const float*)d_in[4];
    float* out = (float*)d_out;

    sumrate_main_kernel<<<GRIDB, THREADS>>>(Hr, Hi, Vr, Vi, np_, out);
}